// round 7
// baseline (speedup 1.0000x reference)
#include <cuda_runtime.h>
#include <cstdint>

// Problem constants
#define Bc   8
#define Tc   256
#define Uc   64
#define Dc   640
#define Vc   1024
#define K2c  1280
#define MOUT (Bc*Tc*Uc)     // 131072 output rows

__device__ __forceinline__ uint32_t f2tf(float x) {
    uint32_t r;
    asm("cvt.rna.tf32.f32 %0, %1;" : "=r"(r) : "f"(x));
    return r;
}
// producer-group barrier (warps 0-7, 256 threads)
__device__ __forceinline__ void barp() {
    asm volatile("bar.sync 1, 256;" ::: "memory");
}

// 91 KB dynamic shared memory, 1 block/SM
struct __align__(16) Smem {
    float    P[64][128];       // 32 KB  P tile (+bias), persistent after phase P
    float    E[2][32][128];    // 32 KB  E slab double buffer
    uint32_t As[64][36];       // 9 KB   A staging (P phase: 64 rows; slabs: 32)
    uint32_t Bs[128][36];      // 18 KB  W staging
};

// ---------------------------------------------------------------------------
// ONE kernel, warp-specialized. grid = (V/128=8, 2*B=16), 512 threads.
//   Block (bx,by): b = by>>1, t0 = (by&1)*128, v-cols [bx*128, +128)
// Phase P  (all 16 warps): P[64u x 128v] = ReLU(pred)@Wp^T + bias -> smem
// Slab loop s=0..4:
//   warps 0-7  (producers): slab-s E gemm (32t x 128v) -> E[s&1]   (s<4)
//   warps 8-15 (consumers): store slab s-1: out = E + P            (s>0)
//   __syncthreads() at each slab boundary; gemm hides under stores.
// ---------------------------------------------------------------------------
__global__ __launch_bounds__(512, 1) void fused_joiner(
    const float* __restrict__ enc,
    const float* __restrict__ pred,
    const float* __restrict__ W,
    const float* __restrict__ bias,
    float4* __restrict__ out,
    const int* __restrict__ slen,
    const int* __restrict__ tlen,
    int writeTail)
{
    extern __shared__ char smem_raw[];
    Smem& sm = *reinterpret_cast<Smem*>(smem_raw);

    const int tid  = threadIdx.x;
    const int warp = tid >> 5;       // 0..15
    const int lane = tid & 31;
    const int g    = lane >> 2;      // 0..7
    const int q    = lane & 3;       // 0..3
    const int bn0  = blockIdx.x * 128;
    const int b    = blockIdx.y >> 1;
    const int bt0  = b * Tc + (blockIdx.y & 1) * 128;

    const int lr = tid >> 3;         // 0..63
    const int lc = (tid & 7) * 4;    // 0,4..28

    // ===================== Phase P: 64 x 128 (all 16 warps) ================
    {
        const int mgP = warp & 3;
        const int ngP = warp >> 2;
        float cP[4][4];
#pragma unroll
        for (int nt = 0; nt < 4; nt++)
#pragma unroll
            for (int r = 0; r < 4; r++) cP[nt][r] = 0.f;

        float4 ra, rw[2];
        ra = *(const float4*)&pred[(size_t)(b * Uc + lr) * Dc + lc];
#pragma unroll
        for (int i = 0; i < 2; i++)
            rw[i] = *(const float4*)&W[(size_t)(bn0 + lr + i * 64) * K2c + Dc + lc];

        for (int k0 = 0; k0 < Dc; k0 += 32) {
            sm.As[lr][lc+0] = f2tf(fmaxf(ra.x, 0.f));
            sm.As[lr][lc+1] = f2tf(fmaxf(ra.y, 0.f));
            sm.As[lr][lc+2] = f2tf(fmaxf(ra.z, 0.f));
            sm.As[lr][lc+3] = f2tf(fmaxf(ra.w, 0.f));
#pragma unroll
            for (int i = 0; i < 2; i++) {
                int row = lr + i * 64;
                sm.Bs[row][lc+0] = f2tf(rw[i].x);
                sm.Bs[row][lc+1] = f2tf(rw[i].y);
                sm.Bs[row][lc+2] = f2tf(rw[i].z);
                sm.Bs[row][lc+3] = f2tf(rw[i].w);
            }
            __syncthreads();
            if (k0 + 32 < Dc) {
                ra = *(const float4*)&pred[(size_t)(b * Uc + lr) * Dc + k0 + 32 + lc];
#pragma unroll
                for (int i = 0; i < 2; i++)
                    rw[i] = *(const float4*)&W[(size_t)(bn0 + lr + i * 64) * K2c + Dc + k0 + 32 + lc];
            }
#pragma unroll
            for (int kk = 0; kk < 4; kk++) {
                uint32_t af[4];
                af[0] = sm.As[mgP*16 + g    ][kk*8 + q    ];
                af[1] = sm.As[mgP*16 + g + 8][kk*8 + q    ];
                af[2] = sm.As[mgP*16 + g    ][kk*8 + q + 4];
                af[3] = sm.As[mgP*16 + g + 8][kk*8 + q + 4];
#pragma unroll
                for (int nt = 0; nt < 4; nt++) {
                    int n = ngP*32 + nt*8 + g;
                    uint32_t b0 = sm.Bs[n][kk*8 + q];
                    uint32_t b1 = sm.Bs[n][kk*8 + q + 4];
                    asm volatile(
                        "mma.sync.aligned.m16n8k8.row.col.f32.tf32.tf32.f32 "
                        "{%0,%1,%2,%3}, {%4,%5,%6,%7}, {%8,%9}, {%0,%1,%2,%3};\n"
                        : "+f"(cP[nt][0]), "+f"(cP[nt][1]), "+f"(cP[nt][2]), "+f"(cP[nt][3])
                        : "r"(af[0]), "r"(af[1]), "r"(af[2]), "r"(af[3]),
                          "r"(b0), "r"(b1));
                }
            }
            __syncthreads();
        }

        // dump P (+bias) to persistent smem
        int r0 = mgP * 16 + g;
#pragma unroll
        for (int nt = 0; nt < 4; nt++) {
            int col = ngP*32 + nt*8 + q*2;
            float b0 = bias[bn0 + col];
            float b1 = bias[bn0 + col + 1];
            sm.P[r0    ][col    ] = cP[nt][0] + b0;
            sm.P[r0    ][col + 1] = cP[nt][1] + b1;
            sm.P[r0 + 8][col    ] = cP[nt][2] + b0;
            sm.P[r0 + 8][col + 1] = cP[nt][3] + b1;
        }
    }
    // NOTE: no barrier needed here; the end-of-slab-0 __syncthreads orders the
    // P writes before the first consumer reads (s=1).

    // ===================== Slab loop: produce / consume ====================
#pragma unroll 1
    for (int s = 0; s < 5; s++) {
        if (warp < 8) {
            // --------------- producer: slab-s E gemm (32 x 128) ------------
            if (s < 4) {
                const int mg = warp & 1;    // 2 m-groups x 16 rows
                const int ng = warp >> 1;   // 4 n-groups x 32 cols
                const int plr = tid >> 3;   // 0..31 (256 producer threads)
                const int plc = (tid & 7) * 4;
                const int arow = bt0 + s * 32 + plr;

                float c[4][4];
#pragma unroll
                for (int nt = 0; nt < 4; nt++)
#pragma unroll
                    for (int r = 0; r < 4; r++) c[nt][r] = 0.f;

                float4 ra, rw[4];
                ra = *(const float4*)&enc[(size_t)arow * Dc + plc];
#pragma unroll
                for (int i = 0; i < 4; i++)
                    rw[i] = *(const float4*)&W[(size_t)(bn0 + plr + i * 32) * K2c + plc];

                for (int k0 = 0; k0 < Dc; k0 += 32) {
                    sm.As[plr][plc+0] = f2tf(fmaxf(ra.x, 0.f));
                    sm.As[plr][plc+1] = f2tf(fmaxf(ra.y, 0.f));
                    sm.As[plr][plc+2] = f2tf(fmaxf(ra.z, 0.f));
                    sm.As[plr][plc+3] = f2tf(fmaxf(ra.w, 0.f));
#pragma unroll
                    for (int i = 0; i < 4; i++) {
                        int row = plr + i * 32;
                        sm.Bs[row][plc+0] = f2tf(rw[i].x);
                        sm.Bs[row][plc+1] = f2tf(rw[i].y);
                        sm.Bs[row][plc+2] = f2tf(rw[i].z);
                        sm.Bs[row][plc+3] = f2tf(rw[i].w);
                    }
                    barp();
                    if (k0 + 32 < Dc) {
                        ra = *(const float4*)&enc[(size_t)arow * Dc + k0 + 32 + plc];
#pragma unroll
                        for (int i = 0; i < 4; i++)
                            rw[i] = *(const float4*)&W[(size_t)(bn0 + plr + i * 32) * K2c + k0 + 32 + plc];
                    }
#pragma unroll
                    for (int kk = 0; kk < 4; kk++) {
                        uint32_t af[4];
                        af[0] = sm.As[mg*16 + g    ][kk*8 + q    ];
                        af[1] = sm.As[mg*16 + g + 8][kk*8 + q    ];
                        af[2] = sm.As[mg*16 + g    ][kk*8 + q + 4];
                        af[3] = sm.As[mg*16 + g + 8][kk*8 + q + 4];
#pragma unroll
                        for (int nt = 0; nt < 4; nt++) {
                            int n = ng*32 + nt*8 + g;
                            uint32_t b0 = sm.Bs[n][kk*8 + q];
                            uint32_t b1 = sm.Bs[n][kk*8 + q + 4];
                            asm volatile(
                                "mma.sync.aligned.m16n8k8.row.col.f32.tf32.tf32.f32 "
                                "{%0,%1,%2,%3}, {%4,%5,%6,%7}, {%8,%9}, {%0,%1,%2,%3};\n"
                                : "+f"(c[nt][0]), "+f"(c[nt][1]), "+f"(c[nt][2]), "+f"(c[nt][3])
                                : "r"(af[0]), "r"(af[1]), "r"(af[2]), "r"(af[3]),
                                  "r"(b0), "r"(b1));
                        }
                    }
                    barp();
                }

                // write slab accumulators to E[s&1]
                int r0 = mg * 16 + g;
                float (*Eb)[128] = sm.E[s & 1];
#pragma unroll
                for (int nt = 0; nt < 4; nt++) {
                    int col = ng*32 + nt*8 + q*2;
                    Eb[r0    ][col    ] = c[nt][0];
                    Eb[r0    ][col + 1] = c[nt][1];
                    Eb[r0 + 8][col    ] = c[nt][2];
                    Eb[r0 + 8][col + 1] = c[nt][3];
                }
            }
        } else {
            // --------------- consumer: store slab s-1 ----------------------
            if (s > 0) {
                const int sl = s - 1;
                const int cw = warp - 8;    // 0..7, 4 t-rows each
                const int vq = lane;
                const float (*Eb)[128] = sm.E[sl & 1];

                float4 e[4];
                size_t ob[4];
#pragma unroll
                for (int ti = 0; ti < 4; ti++) {
                    int tl = cw * 4 + ti;
                    e[ti] = ((const float4*)Eb[tl])[vq];
                    ob[ti] = (size_t)(bt0 + sl * 32 + tl) * (Uc * 256)
                             + blockIdx.x * 32 + vq;
                }
#pragma unroll 4
                for (int u = 0; u < Uc; u++) {
                    float4 p = ((const float4*)sm.P[u])[vq];
#pragma unroll
                    for (int ti = 0; ti < 4; ti++) {
                        float4 r;
                        r.x = e[ti].x + p.x; r.y = e[ti].y + p.y;
                        r.z = e[ti].z + p.z; r.w = e[ti].w + p.w;
                        __stcs(&out[ob[ti] + (size_t)u * 256], r);
                    }
                }
            }
        }
        __syncthreads();
    }

    // passthrough lengths appended after the joint output
    if (writeTail && blockIdx.x == 0 && blockIdx.y == 0 && tid < 16) {
        float* o = (float*)out;
        size_t tb = (size_t)MOUT * Vc;
        if (tid < 8) o[tb + tid] = (float)slen[tid];
        else         o[tb + tid] = (float)tlen[tid - 8];
    }
}

extern "C" void kernel_launch(void* const* d_in, const int* in_sizes, int n_in,
                              void* d_out, int out_size)
{
    const float* enc  = (const float*)d_in[0];  // [B,T,D]
    const int*   slen = (const int*)  d_in[1];  // [B]
    const float* pred = (const float*)d_in[2];  // [B,U,D]
    const int*   tlen = (const int*)  d_in[3];  // [B]
    const float* W    = (const float*)d_in[4];  // [V, 2D]
    const float* bias = (const float*)d_in[5];  // [V]
    float* out = (float*)d_out;

    int smemBytes = (int)sizeof(Smem);
    cudaFuncSetAttribute(fused_joiner,
                         cudaFuncAttributeMaxDynamicSharedMemorySize, smemBytes);

    int writeTail = (out_size >= (int)((size_t)MOUT * Vc + 16)) ? 1 : 0;
    fused_joiner<<<dim3(Vc / 128, 2 * Bc), 512, smemBytes>>>(
        enc, pred, W, bias, (float4*)out, slen, tlen, writeTail);
}

// round 8
// speedup vs baseline: 1.0998x; 1.0998x over previous
#include <cuda_runtime.h>
#include <cstdint>

// Problem constants
#define Bc   8
#define Tc   256
#define Uc   64
#define Dc   640
#define Vc   1024
#define K2c  1280
#define MOUT (Bc*Tc*Uc)     // 131072 output rows
#define NIT  (Dc/32)        // 20 k-iterations

// Pre-transformed operands (tf32 bit patterns stored as float)
__device__ __align__(16) float g_encT [Bc*Tc*Dc];   // relu+tf32(enc)   5.24 MB
__device__ __align__(16) float g_predT[Bc*Uc*Dc];   // relu+tf32(pred)  1.31 MB
__device__ __align__(16) float g_Wtf  [Vc*K2c];     // tf32(W)          5.24 MB

__device__ __forceinline__ uint32_t f2tf(float x) {
    uint32_t r;
    asm("cvt.rna.tf32.f32 %0, %1;" : "=r"(r) : "f"(x));
    return r;
}
__device__ __forceinline__ void cpa(uint32_t dst, const float* src) {
    asm volatile("cp.async.ca.shared.global [%0], [%1], 16;\n"
                 :: "r"(dst), "l"(src));
}
#define CP_COMMIT() asm volatile("cp.async.commit_group;\n" ::: "memory")
#define CP_WAIT2()  asm volatile("cp.async.wait_group 2;\n" ::: "memory")
#define CP_WAIT0()  asm volatile("cp.async.wait_group 0;\n" ::: "memory")

// ---------------------------------------------------------------------------
// Prologue: relu+tf32 transform of enc/pred, tf32 of W; writes length tail.
// ---------------------------------------------------------------------------
#define NE4 (Bc*Tc*Dc/4)
#define NP4 (Bc*Uc*Dc/4)
#define NW4 (Vc*K2c/4)
__global__ __launch_bounds__(256) void transform_kernel(
    const float4* __restrict__ enc,
    const float4* __restrict__ pred,
    const float4* __restrict__ W,
    float* __restrict__ out,
    const int* __restrict__ slen,
    const int* __restrict__ tlen,
    int writeTail)
{
    int idx = blockIdx.x * 256 + threadIdx.x;
    float4 v; float4* dst;
    if (idx < NE4) {
        v = enc[idx];
        v.x = fmaxf(v.x, 0.f); v.y = fmaxf(v.y, 0.f);
        v.z = fmaxf(v.z, 0.f); v.w = fmaxf(v.w, 0.f);
        dst = ((float4*)g_encT) + idx;
    } else if (idx < NE4 + NP4) {
        v = pred[idx - NE4];
        v.x = fmaxf(v.x, 0.f); v.y = fmaxf(v.y, 0.f);
        v.z = fmaxf(v.z, 0.f); v.w = fmaxf(v.w, 0.f);
        dst = ((float4*)g_predT) + (idx - NE4);
    } else if (idx < NE4 + NP4 + NW4) {
        v = W[idx - NE4 - NP4];
        dst = ((float4*)g_Wtf) + (idx - NE4 - NP4);
    } else {
        return;
    }
    uint4 o;
    o.x = f2tf(v.x); o.y = f2tf(v.y); o.z = f2tf(v.z); o.w = f2tf(v.w);
    *(uint4*)dst = o;

    if (writeTail && blockIdx.x == 0 && threadIdx.x < 16) {
        size_t tb = (size_t)MOUT * Vc;
        int t = threadIdx.x;
        if (t < 8) out[tb + t] = (float)slen[t];
        else       out[tb + t] = (float)tlen[t - 8];
    }
}

// 192 KB dynamic shared memory, 1 block/SM
struct __align__(16) Smem {
    float    P[64][128];        // 32 KB  P tile (+bias), persistent
    float    E[32][128];        // 16 KB  store-phase slab
    uint32_t As[4][128][36];    // 72 KB  A staging, 4-stage ring
    uint32_t Bs[4][128][36];    // 72 KB  W staging, 4-stage ring
};

// ---------------------------------------------------------------------------
// Main kernel. grid = (V/128=8, 2*B=16), 512 threads (16 warps), 1 blk/SM.
//   Block (bx,by): b = by>>1, t0 = (by&1)*128, v-cols [bx*128, +128)
// Phase P: P[64u x 128v] -> smem (cp.async pipelined gemm)
// Phase E: cE[128t x 128v] in regs (cp.async pipelined gemm)
// Phase C: 4 slabs of 32 t: out = E + P, 16 warps, evict-first stores
// ---------------------------------------------------------------------------
__global__ __launch_bounds__(512, 1) void fused_joiner(
    const float* __restrict__ bias,
    float4* __restrict__ out)
{
    extern __shared__ char smem_raw[];
    Smem& sm = *reinterpret_cast<Smem*>(smem_raw);

    const int tid  = threadIdx.x;
    const int warp = tid >> 5;
    const int lane = tid & 31;
    const int g    = lane >> 2;
    const int q    = lane & 3;
    const int bn0  = blockIdx.x * 128;
    const int b    = blockIdx.y >> 1;
    const int bt0  = b * Tc + (blockIdx.y & 1) * 128;

    const int lr = tid >> 3;        // 0..63
    const int lc = (tid & 7) * 4;   // 0,4..28

    const uint32_t asB = (uint32_t)__cvta_generic_to_shared(sm.As);
    const uint32_t bsB = (uint32_t)__cvta_generic_to_shared(sm.Bs);
    // byte offset of element [st][row][col]
    auto soff = [](int st, int row, int col) -> uint32_t {
        return (uint32_t)((((st * 128 + row) * 36) + col) * 4);
    };

    // ===================== Phase P: 64 x 128 =====================
    {
        // issue one k-tile into stage st
        auto issueP = [&](int st, int k0) {
            // A: 64 rows x 32 cols, 1 cp.async/thread
            cpa(asB + soff(st, lr, lc),
                &g_predT[(size_t)(b * Uc + lr) * Dc + k0 + lc]);
            // W: 128 rows x 32 cols, 2 cp.async/thread
            cpa(bsB + soff(st, lr, lc),
                &g_Wtf[(size_t)(bn0 + lr) * K2c + Dc + k0 + lc]);
            cpa(bsB + soff(st, lr + 64, lc),
                &g_Wtf[(size_t)(bn0 + lr + 64) * K2c + Dc + k0 + lc]);
        };

        const int mgP = warp & 3;
        const int ngP = warp >> 2;
        float cP[4][4];
#pragma unroll
        for (int nt = 0; nt < 4; nt++)
#pragma unroll
            for (int r = 0; r < 4; r++) cP[nt][r] = 0.f;

        issueP(0, 0);  CP_COMMIT();
        issueP(1, 32); CP_COMMIT();

#pragma unroll 1
        for (int it = 0; it < NIT; it++) {
            const int st = it & 3;
            const int nx = it + 2;
            if (nx < NIT) issueP(nx & 3, nx * 32);
            CP_COMMIT();
            CP_WAIT2();
            __syncthreads();
#pragma unroll
            for (int kk = 0; kk < 4; kk++) {
                uint32_t af[4];
                af[0] = sm.As[st][mgP*16 + g    ][kk*8 + q    ];
                af[1] = sm.As[st][mgP*16 + g + 8][kk*8 + q    ];
                af[2] = sm.As[st][mgP*16 + g    ][kk*8 + q + 4];
                af[3] = sm.As[st][mgP*16 + g + 8][kk*8 + q + 4];
#pragma unroll
                for (int nt = 0; nt < 4; nt++) {
                    int n = ngP*32 + nt*8 + g;
                    uint32_t b0 = sm.Bs[st][n][kk*8 + q];
                    uint32_t b1 = sm.Bs[st][n][kk*8 + q + 4];
                    asm volatile(
                        "mma.sync.aligned.m16n8k8.row.col.f32.tf32.tf32.f32 "
                        "{%0,%1,%2,%3}, {%4,%5,%6,%7}, {%8,%9}, {%0,%1,%2,%3};\n"
                        : "+f"(cP[nt][0]), "+f"(cP[nt][1]), "+f"(cP[nt][2]), "+f"(cP[nt][3])
                        : "r"(af[0]), "r"(af[1]), "r"(af[2]), "r"(af[3]),
                          "r"(b0), "r"(b1));
                }
            }
        }
        CP_WAIT0();
        __syncthreads();

        // dump P (+bias) to persistent smem
        int r0 = mgP * 16 + g;
#pragma unroll
        for (int nt = 0; nt < 4; nt++) {
            int col = ngP*32 + nt*8 + q*2;
            float b0 = bias[bn0 + col];
            float b1 = bias[bn0 + col + 1];
            sm.P[r0    ][col    ] = cP[nt][0] + b0;
            sm.P[r0    ][col + 1] = cP[nt][1] + b1;
            sm.P[r0 + 8][col    ] = cP[nt][2] + b0;
            sm.P[r0 + 8][col + 1] = cP[nt][3] + b1;
        }
    }
    __syncthreads();   // phase boundary: staging buffers free for E phase

    // ===================== Phase E: 128 x 128 =====================
    const int mgE = warp & 3;     // m-tiles {mgE, mgE+4}
    const int ngE = warp >> 2;
    float cE[2][4][4];
#pragma unroll
    for (int mt = 0; mt < 2; mt++)
#pragma unroll
        for (int nt = 0; nt < 4; nt++)
#pragma unroll
            for (int r = 0; r < 4; r++) cE[mt][nt][r] = 0.f;

    {
        auto issueE = [&](int st, int k0) {
            cpa(asB + soff(st, lr, lc),
                &g_encT[(size_t)(bt0 + lr) * Dc + k0 + lc]);
            cpa(asB + soff(st, lr + 64, lc),
                &g_encT[(size_t)(bt0 + lr + 64) * Dc + k0 + lc]);
            cpa(bsB + soff(st, lr, lc),
                &g_Wtf[(size_t)(bn0 + lr) * K2c + k0 + lc]);
            cpa(bsB + soff(st, lr + 64, lc),
                &g_Wtf[(size_t)(bn0 + lr + 64) * K2c + k0 + lc]);
        };

        issueE(0, 0);  CP_COMMIT();
        issueE(1, 32); CP_COMMIT();

#pragma unroll 1
        for (int it = 0; it < NIT; it++) {
            const int st = it & 3;
            const int nx = it + 2;
            if (nx < NIT) issueE(nx & 3, nx * 32);
            CP_COMMIT();
            CP_WAIT2();
            __syncthreads();
#pragma unroll
            for (int kk = 0; kk < 4; kk++) {
                uint32_t af[2][4];
#pragma unroll
                for (int mt = 0; mt < 2; mt++) {
                    int r0 = (mgE + 4*mt) * 16;
                    af[mt][0] = sm.As[st][r0 + g    ][kk*8 + q    ];
                    af[mt][1] = sm.As[st][r0 + g + 8][kk*8 + q    ];
                    af[mt][2] = sm.As[st][r0 + g    ][kk*8 + q + 4];
                    af[mt][3] = sm.As[st][r0 + g + 8][kk*8 + q + 4];
                }
#pragma unroll
                for (int nt = 0; nt < 4; nt++) {
                    int n = ngE*32 + nt*8 + g;
                    uint32_t b0 = sm.Bs[st][n][kk*8 + q];
                    uint32_t b1 = sm.Bs[st][n][kk*8 + q + 4];
#pragma unroll
                    for (int mt = 0; mt < 2; mt++) {
                        asm volatile(
                            "mma.sync.aligned.m16n8k8.row.col.f32.tf32.tf32.f32 "
                            "{%0,%1,%2,%3}, {%4,%5,%6,%7}, {%8,%9}, {%0,%1,%2,%3};\n"
                            : "+f"(cE[mt][nt][0]), "+f"(cE[mt][nt][1]),
                              "+f"(cE[mt][nt][2]), "+f"(cE[mt][nt][3])
                            : "r"(af[mt][0]), "r"(af[mt][1]), "r"(af[mt][2]), "r"(af[mt][3]),
                              "r"(b0), "r"(b1));
                    }
                }
            }
        }
        CP_WAIT0();
        __syncthreads();
    }

    // ===================== Phase C: expand (4 slabs of 32 t) ===============
    const int vq = lane;
#pragma unroll 1
    for (int s = 0; s < 4; s++) {
        // warps owning m-tiles {2s, 2s+1} dump them into sm.E
#pragma unroll
        for (int mt = 0; mt < 2; mt++) {
            int mtile = mgE + 4 * mt;
            if ((mtile >> 1) == s) {
                int r0 = (mtile & 1) * 16 + g;
#pragma unroll
                for (int nt = 0; nt < 4; nt++) {
                    int col = ngE*32 + nt*8 + q*2;
                    sm.E[r0    ][col    ] = cE[mt][nt][0];
                    sm.E[r0    ][col + 1] = cE[mt][nt][1];
                    sm.E[r0 + 8][col    ] = cE[mt][nt][2];
                    sm.E[r0 + 8][col + 1] = cE[mt][nt][3];
                }
            }
        }
        __syncthreads();

        // warp w stores rows {2w, 2w+1}; per u: 1 LDS + 2 STG.cs
        float4 e0 = ((const float4*)sm.E[warp * 2    ])[vq];
        float4 e1 = ((const float4*)sm.E[warp * 2 + 1])[vq];
        size_t ob0 = (size_t)(bt0 + s * 32 + warp * 2) * (Uc * 256)
                     + blockIdx.x * 32 + vq;
        size_t ob1 = ob0 + (size_t)(Uc * 256);
#pragma unroll 4
        for (int u = 0; u < Uc; u++) {
            float4 p = ((const float4*)sm.P[u])[vq];
            float4 r0, r1;
            r0.x = e0.x + p.x; r0.y = e0.y + p.y; r0.z = e0.z + p.z; r0.w = e0.w + p.w;
            r1.x = e1.x + p.x; r1.y = e1.y + p.y; r1.z = e1.z + p.z; r1.w = e1.w + p.w;
            __stcs(&out[ob0 + (size_t)u * 256], r0);
            __stcs(&out[ob1 + (size_t)u * 256], r1);
        }
        __syncthreads();
    }
}

extern "C" void kernel_launch(void* const* d_in, const int* in_sizes, int n_in,
                              void* d_out, int out_size)
{
    const float* enc  = (const float*)d_in[0];  // [B,T,D]
    const int*   slen = (const int*)  d_in[1];  // [B]
    const float* pred = (const float*)d_in[2];  // [B,U,D]
    const int*   tlen = (const int*)  d_in[3];  // [B]
    const float* W    = (const float*)d_in[4];  // [V, 2D]
    const float* bias = (const float*)d_in[5];  // [V]
    float* out = (float*)d_out;

    int writeTail = (out_size >= (int)((size_t)MOUT * Vc + 16)) ? 1 : 0;

    // Prologue: relu+tf32(enc/pred), tf32(W), tail
    int nTot = NE4 + NP4 + NW4;
    transform_kernel<<<(nTot + 255) / 256, 256>>>(
        (const float4*)enc, (const float4*)pred, (const float4*)W,
        out, slen, tlen, writeTail);

    int smemBytes = (int)sizeof(Smem);
    cudaFuncSetAttribute(fused_joiner,
                         cudaFuncAttributeMaxDynamicSharedMemorySize, smemBytes);
    fused_joiner<<<dim3(Vc / 128, 2 * Bc), 512, smemBytes>>>(
        bias, (float4*)out);
}